// round 4
// baseline (speedup 1.0000x reference)
#include <cuda_runtime.h>
#include <math.h>

// Problem constants
#define NN   100000
#define FF   256
#define HH   64
#define CC   40
#define LL   4
#define EE   1200000
#define G3   192            // 3*H
#define KCH  8              // k-chunk rows staged per step in k_gru

// ---------------- scratch (__device__ globals; no allocation allowed) ------
__device__ __align__(16) float g_h   [NN * HH];       // hidden state
__device__ __align__(16) float g_S   [NN * HH];       // aggregated neighbor sum
__device__ __align__(16) float g_Wp  [LL * HH * G3];  // fused convW @ w_ih^T
__device__ __align__(16) float g_whhT[HH * G3];       // w_hh transposed [k][j]
__device__ int g_cnt   [NN];
__device__ int g_rowptr[NN + 1];
__device__ int g_cursor[NN];
__device__ int g_esrc  [EE];
__device__ int g_bsum  [64];
__device__ int g_boff  [64];
__device__ int g_fmt;          // 0 = int64 edge_index layout, 1 = int32 layout

// ---------------- edge dtype detection --------------------------------------
// Inspect odd 32-bit words of the first 2*EE words. If edge_index is int64
// (values < 2^31, little-endian), every odd word is 0. If int32, odd words are
// edge indices (almost surely some nonzero). OR-reduce -> g_fmt.
__global__ void k_zero_misc() {
    int i = blockIdx.x * blockDim.x + threadIdx.x;
    if (i < NN) g_cnt[i] = 0;
    if (i == 0) g_fmt = 0;
}

__global__ void k_detect(const int* __restrict__ ei32) {
    __shared__ int any;
    if (threadIdx.x == 0) any = 0;
    __syncthreads();
    int i = blockIdx.x * blockDim.x + threadIdx.x;
    int v = 0;
    if (i < EE) v = ei32[2 * i + 1];
    if (__syncthreads_or(v != 0)) {
        if (threadIdx.x == 0) atomicOr(&g_fmt, 1);
    }
}

// ---------------- CSR construction -----------------------------------------
__device__ __forceinline__ int edge_src(const int* ei32, int e) {
    return g_fmt ? ei32[e] : ei32[2 * e];
}
__device__ __forceinline__ int edge_dst(const int* ei32, int e) {
    return g_fmt ? ei32[EE + e] : ei32[2 * EE + 2 * e];
}

__global__ void k_hist(const int* __restrict__ ei32) {
    int e = blockIdx.x * blockDim.x + threadIdx.x;
    if (e < EE) {
        int d = edge_dst(ei32, e);
        atomicAdd(&g_cnt[d], 1);
    }
}

// chunk = 2048 per block (256 threads x 8 items)
__global__ void k_scan1() {
    __shared__ int red[256];
    int tid = threadIdx.x;
    int base = blockIdx.x * 2048 + tid * 8;
    int s = 0;
#pragma unroll
    for (int i = 0; i < 8; ++i) {
        int idx = base + i;
        s += (idx < NN) ? g_cnt[idx] : 0;
    }
    red[tid] = s;
    __syncthreads();
    for (int off = 128; off > 0; off >>= 1) {
        if (tid < off) red[tid] += red[tid + off];
        __syncthreads();
    }
    if (tid == 0) g_bsum[blockIdx.x] = red[0];
}

__global__ void k_scan2(int nb) {
    if (threadIdx.x == 0 && blockIdx.x == 0) {
        int run = 0;
        for (int b = 0; b < nb; ++b) {
            int t = g_bsum[b];
            g_boff[b] = run;
            run += t;
        }
        g_rowptr[NN] = run;
    }
}

__global__ void k_scan3() {
    __shared__ int sSum[256];
    int tid = threadIdx.x;
    int base = blockIdx.x * 2048 + tid * 8;
    int v[8];
    int s = 0;
#pragma unroll
    for (int i = 0; i < 8; ++i) {
        int idx = base + i;
        v[i] = (idx < NN) ? g_cnt[idx] : 0;
        s += v[i];
    }
    sSum[tid] = s;
    __syncthreads();
    // Hillis-Steele inclusive scan over 256 thread-sums
    for (int off = 1; off < 256; off <<= 1) {
        int t = (tid >= off) ? sSum[tid - off] : 0;
        __syncthreads();
        sSum[tid] += t;
        __syncthreads();
    }
    int excl = sSum[tid] - s + g_boff[blockIdx.x];
#pragma unroll
    for (int i = 0; i < 8; ++i) {
        int idx = base + i;
        if (idx < NN) {
            g_rowptr[idx] = excl;
            g_cursor[idx] = excl;
        }
        excl += v[i];
    }
}

__global__ void k_fill(const int* __restrict__ ei32) {
    int e = blockIdx.x * blockDim.x + threadIdx.x;
    if (e < EE) {
        int s = edge_src(ei32, e);
        int d = edge_dst(ei32, e);
        int pos = atomicAdd(&g_cursor[d], 1);
        g_esrc[pos] = s;
    }
}

// ---------------- fused weight precompute -----------------------------------
// Wp[l][a][j] = sum_b convW[l][a][b] * w_ih[j][b]   (gi = S @ Wp)
// whhT[b][j]  = w_hh[j][b]                          (gh = h @ whhT)
__global__ void k_wp(const float* __restrict__ conv_w,
                     const float* __restrict__ w_ih,
                     const float* __restrict__ w_hh) {
    int id = blockIdx.x * blockDim.x + threadIdx.x;
    const int NWP = LL * HH * G3;  // 49152
    if (id < NWP) {
        int l = id / (HH * G3);
        int r = id % (HH * G3);
        int a = r / G3;
        int j = r % G3;
        const float* cw = conv_w + (l * HH + a) * HH;
        const float* wi = w_ih + j * HH;
        float s = 0.f;
#pragma unroll 8
        for (int b = 0; b < HH; ++b) s += cw[b] * wi[b];
        g_Wp[id] = s;
    } else if (id < NWP + HH * G3) {
        int r = id - NWP;
        int b = r / G3;
        int j = r % G3;
        g_whhT[r] = w_hh[j * HH + b];
    }
}

// ---------------- input GEMM: h = x @ W_in  [N,256]@[256,64] ----------------
// block: 64 nodes, 256 threads; thread tile 8n x 2j; W_in staged per 64-row chunk
__global__ void __launch_bounds__(256) k_ingemm(const float* __restrict__ x,
                                                const float* __restrict__ win) {
    __shared__ float sW[64 * 64];   // 16KB: W_in rows kc*64..+63
    __shared__ float sX[64 * 64];   // 16KB: x tile
    int tid = threadIdx.x;
    int node0 = blockIdx.x * 64;

    int tn = tid >> 5;   // 0..7  -> nodes tn*8..tn*8+7
    int tj = tid & 31;   // j = tj, tj+32
    float acc[8][2];
#pragma unroll
    for (int i = 0; i < 8; ++i) { acc[i][0] = 0.f; acc[i][1] = 0.f; }

    for (int kc = 0; kc < 4; ++kc) {
        __syncthreads();
        // stage W chunk (1024 float4) + x chunk (1024 float4)
        {
            const float4* w4 = (const float4*)win;
            float4* d4 = (float4*)sW;
            for (int i = tid; i < 1024; i += 256) d4[i] = w4[kc * 1024 + i];
        }
        for (int i = tid; i < 1024; i += 256) {
            int n = i >> 4, c = i & 15;
            int node = node0 + n;
            float4 v = make_float4(0.f, 0.f, 0.f, 0.f);
            if (node < NN)
                v = *(const float4*)(x + (long)node * FF + kc * 64 + c * 4);
            ((float4*)sX)[i] = v;
        }
        __syncthreads();
        const float* sXr = sX + tn * 8 * 64;
#pragma unroll 8
        for (int kk = 0; kk < 64; ++kk) {
            float w0 = sW[kk * 64 + tj];
            float w1 = sW[kk * 64 + tj + 32];
#pragma unroll
            for (int i = 0; i < 8; ++i) {
                float a = sXr[i * 64 + kk];
                acc[i][0] += a * w0;
                acc[i][1] += a * w1;
            }
        }
    }
#pragma unroll
    for (int i = 0; i < 8; ++i) {
        int node = node0 + tn * 8 + i;
        if (node < NN) {
            g_h[node * HH + tj]      = acc[i][0];
            g_h[node * HH + tj + 32] = acc[i][1];
        }
    }
}

// ---------------- aggregation: S[v] = sum_{e:dst=v} h[src[e]] ---------------
__global__ void k_agg() {
    int warp = (blockIdx.x * blockDim.x + threadIdx.x) >> 5;
    int lane = threadIdx.x & 31;
    if (warp >= NN) return;
    int beg = g_rowptr[warp], end = g_rowptr[warp + 1];
    float a0 = 0.f, a1 = 0.f, b0 = 0.f, b1 = 0.f;
    int e = beg;
    for (; e + 1 < end; e += 2) {
        int s0 = g_esrc[e], s1 = g_esrc[e + 1];
        const float* h0 = g_h + (long)s0 * HH;
        const float* h1 = g_h + (long)s1 * HH;
        a0 += h0[lane];      a1 += h0[lane + 32];
        b0 += h1[lane];      b1 += h1[lane + 32];
    }
    if (e < end) {
        const float* h0 = g_h + (long)g_esrc[e] * HH;
        a0 += h0[lane];      a1 += h0[lane + 32];
    }
    g_S[warp * HH + lane]      = a0 + b0;
    g_S[warp * HH + lane + 32] = a1 + b1;
}

// ---------------- fused GRU: gi = S@Wp[l], gh = h@whhT, gates, h update -----
// block: 64 nodes, 512 threads; thread tile 4n x 6j for both GEMMs.
// Weights streamed through smem in KCH-row chunks; gates fully in registers:
// thread (tn,tj) owns, for its 4 nodes, all 6 gate values at dims k=tj, k=tj+32
// (jj = 0,2,4 -> r,z,n at k=tj; jj = 1,3,5 -> r,z,n at k=tj+32).
__global__ void __launch_bounds__(512) k_gru(const float* __restrict__ b_ih,
                                             const float* __restrict__ b_hh,
                                             int layer) {
    __shared__ float sS [64 * HH];    // 16KB
    __shared__ float sH [64 * HH];    // 16KB
    __shared__ float sW1[KCH * G3];   // 6KB  Wp[l] chunk
    __shared__ float sW2[KCH * G3];   // 6KB  whhT chunk
    int tid = threadIdx.x;
    int node0 = blockIdx.x * 64;

    // stage S and h tiles (1024 float4 each)
    for (int i = tid; i < 1024; i += 512) {
        int n = i >> 4, c = i & 15;
        int node = node0 + n;
        float4 vs = make_float4(0.f, 0.f, 0.f, 0.f);
        float4 vh = make_float4(0.f, 0.f, 0.f, 0.f);
        if (node < NN) {
            vs = *(const float4*)(g_S + (long)node * HH + c * 4);
            vh = *(const float4*)(g_h + (long)node * HH + c * 4);
        }
        ((float4*)sS)[i] = vs;
        ((float4*)sH)[i] = vh;
    }

    int tn = tid >> 5;   // 0..15 -> nodes tn*4..+3
    int tj = tid & 31;   // j = tj + 32*jj, jj in [0,6)
    float ai[4][6], ah[4][6];
#pragma unroll
    for (int i = 0; i < 4; ++i)
#pragma unroll
        for (int jj = 0; jj < 6; ++jj) { ai[i][jj] = 0.f; ah[i][jj] = 0.f; }

    const float* sSr = sS + tn * 4 * HH;
    const float* sHr = sH + tn * 4 * HH;
    const float4* wp4 = (const float4*)(g_Wp + layer * HH * G3);
    const float4* wh4 = (const float4*)g_whhT;

    for (int kc = 0; kc < HH / KCH; ++kc) {
        __syncthreads();
        // stage weight chunks: KCH*G3 = 1536 floats = 384 float4 each
        if (tid < KCH * G3 / 4) {
            ((float4*)sW1)[tid] = wp4[kc * (KCH * G3 / 4) + tid];
            ((float4*)sW2)[tid] = wh4[kc * (KCH * G3 / 4) + tid];
        }
        __syncthreads();
#pragma unroll
        for (int k = 0; k < KCH; ++k) {
            int kk = kc * KCH + k;
            float a0 = sSr[kk], a1 = sSr[HH + kk], a2 = sSr[2 * HH + kk], a3 = sSr[3 * HH + kk];
            float h0 = sHr[kk], h1 = sHr[HH + kk], h2 = sHr[2 * HH + kk], h3 = sHr[3 * HH + kk];
            const float* w1r = sW1 + k * G3 + tj;
            const float* w2r = sW2 + k * G3 + tj;
#pragma unroll
            for (int jj = 0; jj < 6; ++jj) {
                float w1 = w1r[jj * 32];
                float w2 = w2r[jj * 32];
                ai[0][jj] += a0 * w1; ai[1][jj] += a1 * w1;
                ai[2][jj] += a2 * w1; ai[3][jj] += a3 * w1;
                ah[0][jj] += h0 * w2; ah[1][jj] += h1 * w2;
                ah[2][jj] += h2 * w2; ah[3][jj] += h3 * w2;
            }
        }
    }

    // gates entirely in registers; biases broadcast from global
    float bi0 = b_ih[tj],            bh0 = b_hh[tj];
    float bi1 = b_ih[tj + 32],       bh1 = b_hh[tj + 32];
    float bi2 = b_ih[HH + tj],       bh2 = b_hh[HH + tj];
    float bi3 = b_ih[HH + tj + 32],  bh3 = b_hh[HH + tj + 32];
    float bi4 = b_ih[2 * HH + tj],      bh4 = b_hh[2 * HH + tj];
    float bi5 = b_ih[2 * HH + tj + 32], bh5 = b_hh[2 * HH + tj + 32];

#pragma unroll
    for (int i = 0; i < 4; ++i) {
        int node = node0 + tn * 4 + i;
        if (node >= NN) continue;
        // k = tj  (jj 0=r, 2=z, 4=n)
        {
            float r = 1.f / (1.f + __expf(-(ai[i][0] + bi0 + ah[i][0] + bh0)));
            float z = 1.f / (1.f + __expf(-(ai[i][2] + bi2 + ah[i][2] + bh2)));
            float nv = tanhf(ai[i][4] + bi4 + r * (ah[i][4] + bh4));
            float hp = sHr[i * HH + tj];
            g_h[node * HH + tj] = (1.f - z) * nv + z * hp;
        }
        // k = tj+32  (jj 1=r, 3=z, 5=n)
        {
            float r = 1.f / (1.f + __expf(-(ai[i][1] + bi1 + ah[i][1] + bh1)));
            float z = 1.f / (1.f + __expf(-(ai[i][3] + bi3 + ah[i][3] + bh3)));
            float nv = tanhf(ai[i][5] + bi5 + r * (ah[i][5] + bh5));
            float hp = sHr[i * HH + tj + 32];
            g_h[node * HH + tj + 32] = (1.f - z) * nv + z * hp;
        }
    }
}

// ---------------- output: logits = h @ W_out, then log_softmax --------------
__global__ void __launch_bounds__(256) k_out(const float* __restrict__ wout,
                                             float* __restrict__ out) {
    __shared__ float sH[64 * HH];    // 16KB
    __shared__ float sW[HH * CC];    // 10KB
    __shared__ float sO[64 * CC];    // 10KB
    int tid = threadIdx.x;
    int node0 = blockIdx.x * 64;

    for (int i = tid; i < 1024; i += 256) {
        int n = i >> 4, c = i & 15;
        int node = node0 + n;
        float4 v = make_float4(0.f, 0.f, 0.f, 0.f);
        if (node < NN) v = *(const float4*)(g_h + (long)node * HH + c * 4);
        ((float4*)sH)[i] = v;
    }
    for (int i = tid; i < HH * CC; i += 256) sW[i] = wout[i];
    __syncthreads();

    int tn = tid >> 3;   // 0..31 -> nodes tn*2, tn*2+1
    int tc = tid & 7;    // c = tc + 8*jj, jj in [0,5)
    float acc[2][5];
#pragma unroll
    for (int i = 0; i < 2; ++i)
#pragma unroll
        for (int jj = 0; jj < 5; ++jj) acc[i][jj] = 0.f;
    const float* sHr = sH + tn * 2 * HH;
#pragma unroll 8
    for (int k = 0; k < HH; ++k) {
        float a0 = sHr[k], a1 = sHr[HH + k];
#pragma unroll
        for (int jj = 0; jj < 5; ++jj) {
            float w = sW[k * CC + tc + 8 * jj];
            acc[0][jj] += a0 * w;
            acc[1][jj] += a1 * w;
        }
    }
#pragma unroll
    for (int i = 0; i < 2; ++i)
#pragma unroll
        for (int jj = 0; jj < 5; ++jj)
            sO[(tn * 2 + i) * CC + tc + 8 * jj] = acc[i][jj];
    __syncthreads();

    // log_softmax: warp per node
    int wid = tid >> 5, lane = tid & 31;
    for (int nn = wid; nn < 64; nn += 8) {
        int node = node0 + nn;
        if (node >= NN) continue;
        float v0 = sO[nn * CC + lane];
        float v1 = (lane < CC - 32) ? sO[nn * CC + 32 + lane] : -1e30f;
        float m = fmaxf(v0, v1);
#pragma unroll
        for (int off = 16; off > 0; off >>= 1)
            m = fmaxf(m, __shfl_xor_sync(0xFFFFFFFFu, m, off));
        float s = expf(v0 - m) + ((lane < CC - 32) ? expf(v1 - m) : 0.f);
#pragma unroll
        for (int off = 16; off > 0; off >>= 1)
            s += __shfl_xor_sync(0xFFFFFFFFu, s, off);
        float lse = m + logf(s);
        out[(long)node * CC + lane] = v0 - lse;
        if (lane < CC - 32) out[(long)node * CC + 32 + lane] = v1 - lse;
    }
}

// ---------------- launch ----------------------------------------------------
extern "C" void kernel_launch(void* const* d_in, const int* in_sizes, int n_in,
                              void* d_out, int out_size) {
    const float* x      = (const float*)d_in[0];
    const int*   ei32   = (const int*)d_in[1];      // int32 OR int64 (detected)
    const float* w_in   = (const float*)d_in[2];
    const float* w_out  = (const float*)d_in[3];
    const float* conv_w = (const float*)d_in[4];
    const float* w_ih   = (const float*)d_in[5];
    const float* w_hh   = (const float*)d_in[6];
    const float* b_ih   = (const float*)d_in[7];
    const float* b_hh   = (const float*)d_in[8];
    float* out = (float*)d_out;

    const int nb_scan = (NN + 2047) / 2048;       // 49
    const int eb = (EE + 255) / 256;              // 4688
    const int nodeb64 = (NN + 63) / 64;           // 1563

    // dtype detect + CSR build
    k_zero_misc<<<(NN + 255) / 256, 256>>>();
    k_detect<<<eb, 256>>>(ei32);
    k_hist<<<eb, 256>>>(ei32);
    k_scan1<<<nb_scan, 256>>>();
    k_scan2<<<1, 32>>>(nb_scan);
    k_scan3<<<nb_scan, 256>>>();
    k_fill<<<eb, 256>>>(ei32);

    // fused weights
    k_wp<<<(LL * HH * G3 + HH * G3 + 255) / 256, 256>>>(conv_w, w_ih, w_hh);

    // h = x @ W_in
    k_ingemm<<<nodeb64, 256>>>(x, w_in);

    // GGNN layers
    for (int l = 0; l < LL; ++l) {
        k_agg<<<(NN * 32 + 255) / 256, 256>>>();
        k_gru<<<nodeb64, 512>>>(b_ih, b_hh, l);
    }

    // output projection + log_softmax
    k_out<<<nodeb64, 256>>>(w_out, out);
    (void)in_sizes; (void)n_in; (void)out_size;
}